// round 1
// baseline (speedup 1.0000x reference)
#include <cuda_runtime.h>
#include <cuda_bf16.h>

#define N_NODES_MAX 100000
#define N_EDGES_MAX 1600000
#define HID 128

// Scratch (no cudaMalloc allowed)
__device__ float g_si[N_NODES_MAX];
__device__ float g_sj[N_NODES_MAX];
__device__ float g_sum[N_NODES_MAX];
__device__ float g_inv[N_NODES_MAX];
__device__ float g_ex[N_EDGES_MAX];

// Zero output accumulator + segment sums
__global__ void k_init(float4* __restrict__ out4, int n4, int n_nodes) {
    int i = blockIdx.x * blockDim.x + threadIdx.x;
    int stride = gridDim.x * blockDim.x;
    for (int j = i; j < n4; j += stride) out4[j] = make_float4(0.f, 0.f, 0.f, 0.f);
    for (int j = i; j < n_nodes; j += stride) g_sum[j] = 0.f;
}

// Per-node attention scores: s_i = x.w_i, s_j = x.w_j  (one warp per node)
__global__ void k_scores(const float4* __restrict__ x4,
                         const float4* __restrict__ wi4,
                         const float4* __restrict__ wj4, int n) {
    int warp = (blockIdx.x * blockDim.x + threadIdx.x) >> 5;
    int lane = threadIdx.x & 31;
    if (warp >= n) return;
    float4 xv = x4[warp * 32 + lane];
    float4 a  = __ldg(&wi4[lane]);
    float4 b  = __ldg(&wj4[lane]);
    float si = xv.x * a.x + xv.y * a.y + xv.z * a.z + xv.w * a.w;
    float sj = xv.x * b.x + xv.y * b.y + xv.z * b.z + xv.w * b.w;
    #pragma unroll
    for (int o = 16; o > 0; o >>= 1) {
        si += __shfl_xor_sync(0xFFFFFFFFu, si, o);
        sj += __shfl_xor_sync(0xFFFFFFFFu, sj, o);
    }
    if (lane == 0) { g_si[warp] = si; g_sj[warp] = sj; }
}

// Per-edge: e = leaky_relu(s_i[h]+s_j[t]); ex = exp(e) (shift-free softmax);
// accumulate segment sums.
__global__ void k_edge(const int* __restrict__ h, const int* __restrict__ t, int ne) {
    int i = blockIdx.x * blockDim.x + threadIdx.x;
    if (i >= ne) return;
    int hi = __ldg(h + i);
    int ti = __ldg(t + i);
    float e = g_si[hi] + g_sj[ti];
    e = (e > 0.f) ? e : 0.01f * e;
    // |e| is O(8): exp without max-subtraction is numerically safe in f32
    float ex = __expf(e);
    g_ex[i] = ex;
    atomicAdd(&g_sum[hi], ex);
}

__global__ void k_inv(int n) {
    int i = blockIdx.x * blockDim.x + threadIdx.x;
    if (i < n) {
        float s = g_sum[i];
        g_inv[i] = (s > 0.f) ? (1.0f / s) : 0.f;
    }
}

// SpMM scatter: out[h] += alpha * x[t]  (one warp per edge, vec4 RED atomics)
__global__ void k_spmm(const float4* __restrict__ x4,
                       const int* __restrict__ h,
                       const int* __restrict__ t,
                       float4* __restrict__ out4, int ne) {
    int e = (blockIdx.x * blockDim.x + threadIdx.x) >> 5;
    int lane = threadIdx.x & 31;
    if (e >= ne) return;
    int hi = __ldg(h + e);
    int ti = __ldg(t + e);
    float a = g_ex[e] * g_inv[hi];
    float4 xv = x4[ti * 32 + lane];
    float4* dst = out4 + hi * 32 + lane;
    asm volatile("red.global.add.v4.f32 [%0], {%1, %2, %3, %4};"
                 :: "l"(dst), "f"(a * xv.x), "f"(a * xv.y), "f"(a * xv.z), "f"(a * xv.w)
                 : "memory");
}

__global__ void k_relu(float4* __restrict__ out4, int n4) {
    int i = blockIdx.x * blockDim.x + threadIdx.x;
    if (i >= n4) return;
    float4 v = out4[i];
    v.x = fmaxf(v.x, 0.f); v.y = fmaxf(v.y, 0.f);
    v.z = fmaxf(v.z, 0.f); v.w = fmaxf(v.w, 0.f);
    out4[i] = v;
}

extern "C" void kernel_launch(void* const* d_in, const int* in_sizes, int n_in,
                              void* d_out, int out_size) {
    const float* x  = (const float*)d_in[0];
    const float* wi = (const float*)d_in[1];
    const float* wj = (const float*)d_in[2];
    const int*   h  = (const int*)d_in[3];
    const int*   t  = (const int*)d_in[4];
    float* out = (float*)d_out;

    int n  = in_sizes[0] / HID;   // nodes
    int ne = in_sizes[3];         // edges
    int n_out4 = out_size / 4;    // float4 elements of output

    // init: zero out + seg sums
    k_init<<<1024, 256>>>((float4*)out, n_out4, n);

    // node scores: one warp per node, 8 warps per block
    int blocks_sc = (n + 7) / 8;
    k_scores<<<blocks_sc, 256>>>((const float4*)x, (const float4*)wi, (const float4*)wj, n);

    // edge pass
    k_edge<<<(ne + 255) / 256, 256>>>(h, t, ne);

    // reciprocal of segment sums
    k_inv<<<(n + 255) / 256, 256>>>(n);

    // spmm: one warp per edge, 8 edges per block
    int blocks_sp = (ne + 7) / 8;
    k_spmm<<<blocks_sp, 256>>>((const float4*)x, h, t, (float4*)out, ne);

    // relu
    k_relu<<<(n_out4 + 255) / 256, 256>>>((float4*)out, n_out4);
}

// round 2
// speedup vs baseline: 2.2397x; 2.2397x over previous
#include <cuda_runtime.h>
#include <cuda_bf16.h>

#define N_NODES_MAX 100000
#define N_EDGES_MAX 1600000
#define HID 128
#define SCAN_CHUNK 1024
#define MAX_CHUNKS ((N_NODES_MAX + SCAN_CHUNK - 1) / SCAN_CHUNK)   // 98

// Scratch (no cudaMalloc allowed)
__device__ float g_si[N_NODES_MAX];
__device__ float g_sj[N_NODES_MAX];
__device__ int   g_cnt[N_NODES_MAX];
__device__ int   g_start[N_NODES_MAX + 1];
__device__ int   g_cursor[N_NODES_MAX];
__device__ int   g_part[MAX_CHUNKS];
__device__ int   g_ts[N_EDGES_MAX];   // t sorted by h

// ---------------------------------------------------------------------------
// 1) Per-node attention scores (one warp per node) + zero histogram counters
__global__ void k_scores(const float4* __restrict__ x4,
                         const float4* __restrict__ wi4,
                         const float4* __restrict__ wj4, int n) {
    int gtid = blockIdx.x * blockDim.x + threadIdx.x;
    int warp = gtid >> 5;
    int lane = threadIdx.x & 31;
    // zero counters (grid covers >= n threads)
    if (gtid < n) g_cnt[gtid] = 0;
    if (warp >= n) return;
    float4 xv = x4[warp * 32 + lane];
    float4 a  = __ldg(&wi4[lane]);
    float4 b  = __ldg(&wj4[lane]);
    float si = xv.x * a.x + xv.y * a.y + xv.z * a.z + xv.w * a.w;
    float sj = xv.x * b.x + xv.y * b.y + xv.z * b.z + xv.w * b.w;
    #pragma unroll
    for (int o = 16; o > 0; o >>= 1) {
        si += __shfl_xor_sync(0xFFFFFFFFu, si, o);
        sj += __shfl_xor_sync(0xFFFFFFFFu, sj, o);
    }
    if (lane == 0) { g_si[warp] = si; g_sj[warp] = sj; }
}

// extra pass to finish zeroing counters when gridDim of k_scores < n threads
__global__ void k_zero_tail(int n) {
    int i = blockIdx.x * blockDim.x + threadIdx.x;
    if (i < n) g_cnt[i] = 0;
}

// ---------------------------------------------------------------------------
// 2) Histogram of h
__global__ void k_hist(const int* __restrict__ h, int ne) {
    int i = blockIdx.x * blockDim.x + threadIdx.x;
    if (i < ne) atomicAdd(&g_cnt[__ldg(h + i)], 1);
}

// ---------------------------------------------------------------------------
// 3) Prefix scan (3 stages)
// 3a: per-chunk sums
__global__ void k_scan_partials(int n) {
    __shared__ int warp_sums[32];
    int chunk = blockIdx.x;
    int i = chunk * SCAN_CHUNK + threadIdx.x;
    int v = (i < n) ? g_cnt[i] : 0;
    // warp reduce
    #pragma unroll
    for (int o = 16; o > 0; o >>= 1) v += __shfl_xor_sync(0xFFFFFFFFu, v, o);
    if ((threadIdx.x & 31) == 0) warp_sums[threadIdx.x >> 5] = v;
    __syncthreads();
    if (threadIdx.x < 32) {
        int s = warp_sums[threadIdx.x];
        #pragma unroll
        for (int o = 16; o > 0; o >>= 1) s += __shfl_xor_sync(0xFFFFFFFFu, s, o);
        if (threadIdx.x == 0) g_part[chunk] = s;
    }
}

// 3b: exclusive scan of chunk sums (single block)
__global__ void k_scan_top(int nchunks) {
    __shared__ int sh[MAX_CHUNKS];
    for (int i = threadIdx.x; i < nchunks; i += blockDim.x) sh[i] = g_part[i];
    __syncthreads();
    if (threadIdx.x == 0) {   // serial in smem: ~98 adds, negligible
        int run = 0;
        for (int i = 0; i < nchunks; i++) { int v = sh[i]; sh[i] = run; run += v; }
    }
    __syncthreads();
    for (int i = threadIdx.x; i < nchunks; i += blockDim.x) g_part[i] = sh[i];
}

// 3c: intra-chunk exclusive scan + chunk offset -> g_start, g_cursor
__global__ void k_scan_final(int n, int ne) {
    __shared__ int warp_sums[32];
    int chunk = blockIdx.x;
    int i = chunk * SCAN_CHUNK + threadIdx.x;
    int lane = threadIdx.x & 31;
    int wid = threadIdx.x >> 5;
    int v = (i < n) ? g_cnt[i] : 0;
    // warp inclusive scan
    int sc = v;
    #pragma unroll
    for (int o = 1; o < 32; o <<= 1) {
        int u = __shfl_up_sync(0xFFFFFFFFu, sc, o);
        if (lane >= o) sc += u;
    }
    if (lane == 31) warp_sums[wid] = sc;
    __syncthreads();
    if (threadIdx.x < 32) {
        int s = warp_sums[threadIdx.x];
        #pragma unroll
        for (int o = 1; o < 32; o <<= 1) {
            int u = __shfl_up_sync(0xFFFFFFFFu, s, o);
            if (lane >= o) s += u;
        }
        warp_sums[threadIdx.x] = s - warp_sums[threadIdx.x];  // exclusive
    }
    __syncthreads();
    int excl = sc - v + warp_sums[wid] + g_part[chunk];
    if (i < n) { g_start[i] = excl; g_cursor[i] = excl; }
    if (i == 0) g_start[n] = ne;
}

// ---------------------------------------------------------------------------
// 4) Scatter t into h-sorted order
__global__ void k_scatter(const int* __restrict__ h, const int* __restrict__ t, int ne) {
    int i = blockIdx.x * blockDim.x + threadIdx.x;
    if (i >= ne) return;
    int hi = __ldg(h + i);
    int pos = atomicAdd(&g_cursor[hi], 1);
    g_ts[pos] = __ldg(t + i);
}

// ---------------------------------------------------------------------------
// 5) Fused gather: per node r, iterate its edges; compute exp(lrelu(si+sj)),
//    accumulate Sum(ex) and Sum(ex * x[t]); write relu(acc/sum). One warp/node.
__global__ void k_gather(const float4* __restrict__ x4,
                         float4* __restrict__ out4, int n) {
    int r = (blockIdx.x * blockDim.x + threadIdx.x) >> 5;
    int lane = threadIdx.x & 31;
    if (r >= n) return;
    int beg = g_start[r];
    int end = g_start[r + 1];
    float si = g_si[r];
    float4 acc = make_float4(0.f, 0.f, 0.f, 0.f);
    float ssum = 0.f;

    int j = beg;
    // unroll by 2 for MLP on the x gathers
    for (; j + 2 <= end; j += 2) {
        int t0 = g_ts[j];
        int t1 = g_ts[j + 1];
        float e0 = si + g_sj[t0];
        float e1 = si + g_sj[t1];
        e0 = (e0 > 0.f) ? e0 : 0.01f * e0;
        e1 = (e1 > 0.f) ? e1 : 0.01f * e1;
        float ex0 = __expf(e0);
        float ex1 = __expf(e1);
        float4 xv0 = x4[(size_t)t0 * 32 + lane];
        float4 xv1 = x4[(size_t)t1 * 32 + lane];
        ssum += ex0 + ex1;
        acc.x += ex0 * xv0.x + ex1 * xv1.x;
        acc.y += ex0 * xv0.y + ex1 * xv1.y;
        acc.z += ex0 * xv0.z + ex1 * xv1.z;
        acc.w += ex0 * xv0.w + ex1 * xv1.w;
    }
    if (j < end) {
        int t0 = g_ts[j];
        float e0 = si + g_sj[t0];
        e0 = (e0 > 0.f) ? e0 : 0.01f * e0;
        float ex0 = __expf(e0);
        float4 xv0 = x4[(size_t)t0 * 32 + lane];
        ssum += ex0;
        acc.x += ex0 * xv0.x; acc.y += ex0 * xv0.y;
        acc.z += ex0 * xv0.z; acc.w += ex0 * xv0.w;
    }
    float rinv = (ssum > 0.f) ? (1.0f / ssum) : 0.f;
    float4 o;
    o.x = fmaxf(acc.x * rinv, 0.f);
    o.y = fmaxf(acc.y * rinv, 0.f);
    o.z = fmaxf(acc.z * rinv, 0.f);
    o.w = fmaxf(acc.w * rinv, 0.f);
    out4[(size_t)r * 32 + lane] = o;
}

// ---------------------------------------------------------------------------
extern "C" void kernel_launch(void* const* d_in, const int* in_sizes, int n_in,
                              void* d_out, int out_size) {
    const float* x  = (const float*)d_in[0];
    const float* wi = (const float*)d_in[1];
    const float* wj = (const float*)d_in[2];
    const int*   h  = (const int*)d_in[3];
    const int*   t  = (const int*)d_in[4];
    float* out = (float*)d_out;

    int n  = in_sizes[0] / HID;   // nodes
    int ne = in_sizes[3];         // edges

    int blocks_sc = (n + 7) / 8;            // warp per node, 8 warps/block
    k_scores<<<blocks_sc, 256>>>((const float4*)x, (const float4*)wi, (const float4*)wj, n);
    // k_scores zeroes g_cnt[0 .. blocks_sc*256); cover the rest if needed
    int covered = blocks_sc * 256;
    if (covered < n)
        k_zero_tail<<<(n - covered + 255) / 256, 256>>>(n);

    k_hist<<<(ne + 255) / 256, 256>>>(h, ne);

    int nchunks = (n + SCAN_CHUNK - 1) / SCAN_CHUNK;
    k_scan_partials<<<nchunks, SCAN_CHUNK>>>(n);
    k_scan_top<<<1, 128>>>(nchunks);
    k_scan_final<<<nchunks, SCAN_CHUNK>>>(n, ne);

    k_scatter<<<(ne + 255) / 256, 256>>>(h, t, ne);

    k_gather<<<(n + 7) / 8, 256>>>((const float4*)x, (float4*)out, n);
}